// round 11
// baseline (speedup 1.0000x reference)
#include <cuda_runtime.h>
#include <cuda_fp16.h>
#include <cstdint>

#define C_DIM  256
#define L_DIM  4096
#define LM_DIM 36864
#define B_DIM  4

__device__ float    g_M[C_DIM * C_DIM];              // M[c1][c2] fp32
__device__ uint32_t g_Bpk[128 * 256 * 2];            // [k2][n]{hi, lo*2048} f16x2
__device__ float    g_U[B_DIM * C_DIM * L_DIM];      // U[b][c2][l] (x256 scale)

// ---------------- helpers ----------------
__device__ __forceinline__ uint32_t smem_u32(const void* p) {
    uint32_t a;
    asm("{ .reg .u64 t; cvta.to.shared.u64 t, %1; cvt.u32.u64 %0, t; }" : "=r"(a) : "l"(p));
    return a;
}
__device__ __forceinline__ void cp16(uint32_t dst, const void* src) {
    asm volatile("cp.async.cg.shared.global [%0], [%1], 16;" :: "r"(dst), "l"(src) : "memory");
}
__device__ __forceinline__ void cp_commit() {
    asm volatile("cp.async.commit_group;" ::: "memory");
}
template <int N>
__device__ __forceinline__ void cp_wait() {
    asm volatile("cp.async.wait_group %0;" :: "n"(N) : "memory");
}
// split x -> f16 hi + f16 lo*2048 (lo scaled out of subnormal range)
__device__ __forceinline__ void split_hl(float x, uint32_t& h, uint32_t& l) {
    __half hh = __float2half_rn(x);
    float lo = (x - __half2float(hh)) * 2048.0f;
    h = (uint32_t)__half_as_ushort(hh);
    l = (uint32_t)__half_as_ushort(__float2half_rn(lo));
}
__device__ __forceinline__ void mma16(float* d, const uint32_t* a, const uint32_t* b) {
    asm volatile(
        "mma.sync.aligned.m16n8k16.row.col.f32.f16.f16.f32 "
        "{%0,%1,%2,%3}, {%4,%5,%6,%7}, {%8,%9}, {%0,%1,%2,%3};"
        : "+f"(d[0]), "+f"(d[1]), "+f"(d[2]), "+f"(d[3])
        : "r"(a[0]), "r"(a[1]), "r"(a[2]), "r"(a[3]), "r"(b[0]), "r"(b[1]));
}

// ---------------- Kernel 1: M[c1][c2], 8-way k-split + atomicAdd ----------------
__global__ __launch_bounds__(256) void k1_M(const float* __restrict__ W1,
                                            const float* __restrict__ W2) {
    __shared__ float A[32][33];
    __shared__ float Bs[32][33];
    const int t = threadIdx.x;
    const int c2_0 = blockIdx.x * 32, c1_0 = blockIdx.y * 32, kk = blockIdx.z * 32;
    {
        int r = t >> 3, c4 = (t & 7) * 4;
        float4 a = *(const float4*)&W1[(c1_0 + r) * 768 + kk + c4];
        A[r][c4] = a.x; A[r][c4 + 1] = a.y; A[r][c4 + 2] = a.z; A[r][c4 + 3] = a.w;
        float4 b = *(const float4*)&W2[(c2_0 + r) * 768 + 256 + kk + c4];
        Bs[r][c4] = b.x; Bs[r][c4 + 1] = b.y; Bs[r][c4 + 2] = b.z; Bs[r][c4 + 3] = b.w;
    }
    __syncthreads();
    const int ty = t >> 4, tx = t & 15;
    float a00 = 0.f, a01 = 0.f, a10 = 0.f, a11 = 0.f;
    #pragma unroll
    for (int k = 0; k < 32; ++k) {
        float x0 = A[ty * 2][k], x1 = A[ty * 2 + 1][k];
        float y0 = Bs[tx * 2][k], y1 = Bs[tx * 2 + 1][k];
        a00 += x0 * y0; a01 += x0 * y1; a10 += x1 * y0; a11 += x1 * y1;
    }
    atomicAdd(&g_M[(c1_0 + ty * 2)     * 256 + c2_0 + tx * 2],     a00);
    atomicAdd(&g_M[(c1_0 + ty * 2)     * 256 + c2_0 + tx * 2 + 1], a01);
    atomicAdd(&g_M[(c1_0 + ty * 2 + 1) * 256 + c2_0 + tx * 2],     a10);
    atomicAdd(&g_M[(c1_0 + ty * 2 + 1) * 256 + c2_0 + tx * 2 + 1], a11);
}

// ---------------- Kernel 1b: pack M*256 -> f16 {hi, lo*2048} k-pairs [k2][n] ----------------
__global__ __launch_bounds__(256) void k1b_pack() {
    const int idx = blockIdx.x * 256 + threadIdx.x;     // 32768 = 128 k2 x 256 n
    const int k2 = idx >> 8, n = idx & 255;
    float x0 = g_M[(2 * k2)     * 256 + n] * 256.0f;
    float x1 = g_M[(2 * k2 + 1) * 256 + n] * 256.0f;
    uint32_t h0, l0, h1, l1;
    split_hl(x0, h0, l0);
    split_hl(x1, h1, l1);
    uint2 v;
    v.x = h0 | (h1 << 16);
    v.y = l0 | (l1 << 16);
    *(uint2*)&g_Bpk[idx * 2] = v;
}

// ---------------- Kernel 2: U = HSI^T x M, f16 split w/ scaled-lo cross accumulators ----------------
// Tile 128 l x 64 c2; K=256 in 8 chunks of 32 (16 k-pairs each).
// Grid: x = c2-tile (4, fastest -> concurrent blocks share A via L2), y = l-tile, z = b.
#define PAU 264
#define PAR 136
#define PBU 136
#define OFF_APK 0
#define OFF_AR0 (16 * PAU)
#define OFF_AR1 (OFF_AR0 + 32 * PAR)
#define OFF_B0  (OFF_AR1 + 32 * PAR)
#define OFF_B1  (OFF_B0 + 16 * PBU)
#define K2_F    (OFF_B1 + 16 * PBU)
#define K2_SMEM (K2_F * 4)                 // 69120 B
#define UPIT 132

__global__ __launch_bounds__(256, 2) void k2_U(const float* __restrict__ HSI) {
    extern __shared__ uint32_t smu[];
    float* smf = (float*)smu;
    const int t = threadIdx.x, wid = t >> 5, lane = t & 31;
    const int g = lane >> 2, t4 = lane & 3;
    const int b = blockIdx.z, c2_0 = blockIdx.x * 64, l0 = blockIdx.y * 128;
    const float* Hb = HSI + (size_t)b * C_DIM * L_DIM;
    const uint32_t sbase = smem_u32(smu);
    const int mw = (wid >> 1) * 32;
    const int nw = (wid & 1) * 32;

    float dh[2][4][4], dc[2][4][4];
    #pragma unroll
    for (int mt = 0; mt < 2; ++mt)
        #pragma unroll
        for (int nt = 0; nt < 4; ++nt)
            #pragma unroll
            for (int i = 0; i < 4; ++i) { dh[mt][nt][i] = 0.f; dc[mt][nt][i] = 0.f; }

    {
        #pragma unroll
        for (int q = 0; q < 4; ++q) {
            int idx = t + q * 256;
            int r = idx >> 5, c = (idx & 31) * 4;
            cp16(sbase + (uint32_t)((OFF_AR0 + r * PAR + c) * 4),
                 &Hb[(size_t)r * L_DIM + l0 + c]);
        }
        #pragma unroll
        for (int q = 0; q < 2; ++q) {
            int idx = t + q * 256;
            int r = idx >> 5, c = (idx & 31) * 4;
            cp16(sbase + (uint32_t)((OFF_B0 + r * PBU + c) * 4),
                 &g_Bpk[(r * 256 + c2_0) * 2 + c]);
        }
        cp_commit();
    }

    for (int ch = 0; ch < 8; ++ch) {
        if (ch < 7) {
            const int p = (ch + 1) & 1;
            const int kk = (ch + 1) * 32, k2r0 = (ch + 1) * 16;
            const int offA = p ? OFF_AR1 : OFF_AR0;
            const int offB = p ? OFF_B1 : OFF_B0;
            #pragma unroll
            for (int q = 0; q < 4; ++q) {
                int idx = t + q * 256;
                int r = idx >> 5, c = (idx & 31) * 4;
                cp16(sbase + (uint32_t)((offA + r * PAR + c) * 4),
                     &Hb[(size_t)(kk + r) * L_DIM + l0 + c]);
            }
            #pragma unroll
            for (int q = 0; q < 2; ++q) {
                int idx = t + q * 256;
                int r = idx >> 5, c = (idx & 31) * 4;
                cp16(sbase + (uint32_t)((offB + r * PBU + c) * 4),
                     &g_Bpk[((k2r0 + r) * 256 + c2_0) * 2 + c]);
            }
            cp_commit();
            cp_wait<1>();
        } else {
            cp_wait<0>();
        }
        __syncthreads();

        {
            const float* Ar = smf + ((ch & 1) ? OFF_AR1 : OFF_AR0);
            #pragma unroll
            for (int q = 0; q < 8; ++q) {
                int idx = t + q * 256;
                int k2r = idx >> 7, m = idx & 127;
                float x0 = Ar[(2 * k2r)     * PAR + m];
                float x1 = Ar[(2 * k2r + 1) * PAR + m];
                uint32_t h0, lo0, h1, lo1;
                split_hl(x0, h0, lo0);
                split_hl(x1, h1, lo1);
                uint2 v;
                v.x = h0 | (h1 << 16);
                v.y = lo0 | (lo1 << 16);
                *(uint2*)&smu[OFF_APK + k2r * PAU + 2 * m] = v;
            }
        }
        __syncthreads();

        const uint32_t* Bp = smu + ((ch & 1) ? OFF_B1 : OFF_B0);

        #pragma unroll
        for (int s = 0; s < 2; ++s) {
            const int kr0 = 8 * s + t4, kr1 = kr0 + 4;
            uint32_t ah[2][4], al[2][4];
            #pragma unroll
            for (int mt = 0; mt < 2; ++mt) {
                const int m0 = mw + 16 * mt + g;
                uint2 p0 = *(const uint2*)&smu[OFF_APK + kr0 * PAU + 2 * m0];
                uint2 p1 = *(const uint2*)&smu[OFF_APK + kr0 * PAU + 2 * (m0 + 8)];
                uint2 p2 = *(const uint2*)&smu[OFF_APK + kr1 * PAU + 2 * m0];
                uint2 p3 = *(const uint2*)&smu[OFF_APK + kr1 * PAU + 2 * (m0 + 8)];
                ah[mt][0] = p0.x; al[mt][0] = p0.y;
                ah[mt][1] = p1.x; al[mt][1] = p1.y;
                ah[mt][2] = p2.x; al[mt][2] = p2.y;
                ah[mt][3] = p3.x; al[mt][3] = p3.y;
            }
            uint32_t bh[4][2], bl[4][2];
            #pragma unroll
            for (int q = 0; q < 4; ++q) {
                const int n0 = nw + 8 * q + g;
                uint2 p0 = *(const uint2*)&Bp[kr0 * PBU + 2 * n0];
                uint2 p1 = *(const uint2*)&Bp[kr1 * PBU + 2 * n0];
                bh[q][0] = p0.x; bl[q][0] = p0.y;
                bh[q][1] = p1.x; bl[q][1] = p1.y;
            }
            #pragma unroll
            for (int mt = 0; mt < 2; ++mt)
                #pragma unroll
                for (int q = 0; q < 4; ++q)
                    mma16(dh[mt][q], ah[mt], bh[q]);
            #pragma unroll
            for (int mt = 0; mt < 2; ++mt)
                #pragma unroll
                for (int q = 0; q < 4; ++q)
                    mma16(dc[mt][q], ah[mt], bl[q]);
            #pragma unroll
            for (int mt = 0; mt < 2; ++mt)
                #pragma unroll
                for (int q = 0; q < 4; ++q)
                    mma16(dc[mt][q], al[mt], bh[q]);
        }
    }
    __syncthreads();

    // combine + epilogue
    float* Usm = smf;
    float* Ub = g_U + (size_t)b * C_DIM * L_DIM;
    const float inv = 4.8828125e-4f;   // 1/2048
    #pragma unroll
    for (int mt = 0; mt < 2; ++mt) {
        int row0 = mw + 16 * mt + g;
        #pragma unroll
        for (int nt = 0; nt < 4; ++nt) {
            int col0 = nw + 8 * nt + 2 * t4;
            Usm[col0 * UPIT + row0]           = fmaf(dc[mt][nt][0], inv, dh[mt][nt][0]);
            Usm[(col0 + 1) * UPIT + row0]     = fmaf(dc[mt][nt][1], inv, dh[mt][nt][1]);
            Usm[col0 * UPIT + row0 + 8]       = fmaf(dc[mt][nt][2], inv, dh[mt][nt][2]);
            Usm[(col0 + 1) * UPIT + row0 + 8] = fmaf(dc[mt][nt][3], inv, dh[mt][nt][3]);
        }
    }
    __syncthreads();
    for (int i = t; i < 64 * 32; i += 256) {
        int c2 = i >> 5, q = (i & 31) * 4;
        float4 v = *(const float4*)&Usm[c2 * UPIT + q];
        *(float4*)&Ub[(size_t)(c2_0 + c2) * L_DIM + l0 + q] = v;
    }
}

// ---------------- Kernel 3: scores + argmax, depth-8 register prefetch pipeline ----------------
#define K3_SMEM (256 * 68 * 4)   // us[256][68]

__global__ __launch_bounds__(288, 3) void k3_attn(const float* __restrict__ MSI,
                                                  float* __restrict__ out) {
    extern __shared__ float us[];          // [c2][l] pitch 68
    __shared__ float sc[576];
    const int t = threadIdx.x;
    const int b = blockIdx.y;
    const int l0 = blockIdx.x * 64;
    const float* Ub = g_U + (size_t)b * C_DIM * L_DIM;

    for (int i = t; i < 256 * 64; i += 288) {
        int c2 = i >> 6, l = i & 63;
        us[c2 * 68 + l] = Ub[(size_t)c2 * L_DIM + l0 + l];
    }
    __syncthreads();

    const int ll0 = (2 * t) / 9, ll1 = (2 * t + 1) / 9;
    const float* mp = MSI + (size_t)b * C_DIM * LM_DIM + (size_t)l0 * 9 + 2 * t;
    float acc0 = 0.f, acc1 = 0.f;

    float2 buf[8];
    #pragma unroll
    for (int j = 0; j < 8; ++j)
        buf[j] = __ldg((const float2*)&mp[(size_t)j * LM_DIM]);

    for (int c2 = 0; c2 < 248; c2 += 8) {
        #pragma unroll
        for (int j = 0; j < 8; ++j) {
            float2 nxt = __ldg((const float2*)&mp[(size_t)(c2 + 8 + j) * LM_DIM]);
            acc0 += us[(c2 + j) * 68 + ll0] * buf[j].x;
            acc1 += us[(c2 + j) * 68 + ll1] * buf[j].y;
            buf[j] = nxt;
        }
    }
    #pragma unroll
    for (int j = 0; j < 8; ++j) {
        acc0 += us[(248 + j) * 68 + ll0] * buf[j].x;
        acc1 += us[(248 + j) * 68 + ll1] * buf[j].y;
    }

    sc[2 * t] = acc0;
    sc[2 * t + 1] = acc1;
    __syncthreads();

    if (t < 64) {
        float best = sc[t * 9];
        int bn = 0;
        #pragma unroll
        for (int j = 1; j < 9; ++j) {
            float v = sc[t * 9 + j];
            if (v > best) { best = v; bn = j; }   // strict > = first max (jnp.argmax)
        }
        float2 o = make_float2((float)(bn / 3) - 1.f, (float)(bn % 3) - 1.f);
        *(float2*)&out[(size_t)(b * L_DIM + l0 + t) * 2] = o;
    }
}

// ---------------- launch ----------------
extern "C" void kernel_launch(void* const* d_in, const int* in_sizes, int n_in,
                              void* d_out, int out_size) {
    const float* HSI = (const float*)d_in[2];
    const float* MSI = (const float*)d_in[3];
    const float* W1  = (const float*)d_in[4];
    const float* W2  = (const float*)d_in[5];
    float* out = (float*)d_out;

    void* mp = nullptr;
    cudaGetSymbolAddress(&mp, g_M);
    cudaMemsetAsync(mp, 0, C_DIM * C_DIM * sizeof(float), 0);

    k1_M<<<dim3(8, 8, 8), 256>>>(W1, W2);
    k1b_pack<<<128, 256>>>();

    cudaFuncSetAttribute(k2_U, cudaFuncAttributeMaxDynamicSharedMemorySize, K2_SMEM);
    k2_U<<<dim3(4, 32, 4), 256, K2_SMEM>>>(HSI);

    cudaFuncSetAttribute(k3_attn, cudaFuncAttributeMaxDynamicSharedMemorySize, K3_SMEM);
    k3_attn<<<dim3(64, 4), 288, K3_SMEM>>>(MSI, out);
}

// round 12
// speedup vs baseline: 1.1538x; 1.1538x over previous
#include <cuda_runtime.h>
#include <cuda_fp16.h>
#include <cstdint>

#define C_DIM  256
#define L_DIM  4096
#define LM_DIM 36864
#define B_DIM  4

__device__ float    g_M[C_DIM * C_DIM];              // M[c1][c2] fp32
__device__ uint32_t g_Bpk[128 * 256 * 2];            // [k2][n]{hi, lo*2048} f16x2
__device__ float    g_U[B_DIM * C_DIM * L_DIM];      // U[b][c2][l] (x256 scale)

// ---------------- helpers ----------------
__device__ __forceinline__ uint32_t smem_u32(const void* p) {
    uint32_t a;
    asm("{ .reg .u64 t; cvta.to.shared.u64 t, %1; cvt.u32.u64 %0, t; }" : "=r"(a) : "l"(p));
    return a;
}
__device__ __forceinline__ void cp16(uint32_t dst, const void* src) {
    asm volatile("cp.async.cg.shared.global [%0], [%1], 16;" :: "r"(dst), "l"(src) : "memory");
}
__device__ __forceinline__ void cp_commit() {
    asm volatile("cp.async.commit_group;" ::: "memory");
}
template <int N>
__device__ __forceinline__ void cp_wait() {
    asm volatile("cp.async.wait_group %0;" :: "n"(N) : "memory");
}
// split x -> f16 hi + f16 lo*2048 (lo scaled out of subnormal range)
__device__ __forceinline__ void split_hl(float x, uint32_t& h, uint32_t& l) {
    __half hh = __float2half_rn(x);
    float lo = (x - __half2float(hh)) * 2048.0f;
    h = (uint32_t)__half_as_ushort(hh);
    l = (uint32_t)__half_as_ushort(__float2half_rn(lo));
}
__device__ __forceinline__ void mma16(float* d, const uint32_t* a, const uint32_t* b) {
    asm volatile(
        "mma.sync.aligned.m16n8k16.row.col.f32.f16.f16.f32 "
        "{%0,%1,%2,%3}, {%4,%5,%6,%7}, {%8,%9}, {%0,%1,%2,%3};"
        : "+f"(d[0]), "+f"(d[1]), "+f"(d[2]), "+f"(d[3])
        : "r"(a[0]), "r"(a[1]), "r"(a[2]), "r"(a[3]), "r"(b[0]), "r"(b[1]));
}

// ---------------- Kernel 1: M[c1][c2], 8-way k-split + atomicAdd ----------------
__global__ __launch_bounds__(256) void k1_M(const float* __restrict__ W1,
                                            const float* __restrict__ W2) {
    __shared__ float A[32][33];
    __shared__ float Bs[32][33];
    const int t = threadIdx.x;
    const int c2_0 = blockIdx.x * 32, c1_0 = blockIdx.y * 32, kk = blockIdx.z * 32;
    {
        int r = t >> 3, c4 = (t & 7) * 4;
        float4 a = *(const float4*)&W1[(c1_0 + r) * 768 + kk + c4];
        A[r][c4] = a.x; A[r][c4 + 1] = a.y; A[r][c4 + 2] = a.z; A[r][c4 + 3] = a.w;
        float4 b = *(const float4*)&W2[(c2_0 + r) * 768 + 256 + kk + c4];
        Bs[r][c4] = b.x; Bs[r][c4 + 1] = b.y; Bs[r][c4 + 2] = b.z; Bs[r][c4 + 3] = b.w;
    }
    __syncthreads();
    const int ty = t >> 4, tx = t & 15;
    float a00 = 0.f, a01 = 0.f, a10 = 0.f, a11 = 0.f;
    #pragma unroll
    for (int k = 0; k < 32; ++k) {
        float x0 = A[ty * 2][k], x1 = A[ty * 2 + 1][k];
        float y0 = Bs[tx * 2][k], y1 = Bs[tx * 2 + 1][k];
        a00 += x0 * y0; a01 += x0 * y1; a10 += x1 * y0; a11 += x1 * y1;
    }
    atomicAdd(&g_M[(c1_0 + ty * 2)     * 256 + c2_0 + tx * 2],     a00);
    atomicAdd(&g_M[(c1_0 + ty * 2)     * 256 + c2_0 + tx * 2 + 1], a01);
    atomicAdd(&g_M[(c1_0 + ty * 2 + 1) * 256 + c2_0 + tx * 2],     a10);
    atomicAdd(&g_M[(c1_0 + ty * 2 + 1) * 256 + c2_0 + tx * 2 + 1], a11);
}

// ---------------- Kernel 1b: pack M*256 -> f16 {hi, lo*2048} k-pairs [k2][n] ----------------
__global__ __launch_bounds__(256) void k1b_pack() {
    const int idx = blockIdx.x * 256 + threadIdx.x;
    const int k2 = idx >> 8, n = idx & 255;
    float x0 = g_M[(2 * k2)     * 256 + n] * 256.0f;
    float x1 = g_M[(2 * k2 + 1) * 256 + n] * 256.0f;
    uint32_t h0, l0, h1, l1;
    split_hl(x0, h0, l0);
    split_hl(x1, h1, l1);
    uint2 v;
    v.x = h0 | (h1 << 16);
    v.y = l0 | (l1 << 16);
    *(uint2*)&g_Bpk[idx * 2] = v;
}

// ---------------- Kernel 2: U = HSI^T x M (r10-proven, unchanged) ----------------
#define PAU 264
#define PAR 136
#define PBU 136
#define OFF_APK 0
#define OFF_AR0 (16 * PAU)
#define OFF_AR1 (OFF_AR0 + 32 * PAR)
#define OFF_B0  (OFF_AR1 + 32 * PAR)
#define OFF_B1  (OFF_B0 + 16 * PBU)
#define K2_F    (OFF_B1 + 16 * PBU)
#define K2_SMEM (K2_F * 4)                 // 69120 B
#define UPIT 132

__global__ __launch_bounds__(256, 2) void k2_U(const float* __restrict__ HSI) {
    extern __shared__ uint32_t smu[];
    float* smf = (float*)smu;
    const int t = threadIdx.x, wid = t >> 5, lane = t & 31;
    const int g = lane >> 2, t4 = lane & 3;
    const int b = blockIdx.z, c2_0 = blockIdx.y * 64, l0 = blockIdx.x * 128;
    const float* Hb = HSI + (size_t)b * C_DIM * L_DIM;
    const uint32_t sbase = smem_u32(smu);
    const int mw = (wid >> 1) * 32;
    const int nw = (wid & 1) * 32;

    float dh[2][4][4], dc[2][4][4];
    #pragma unroll
    for (int mt = 0; mt < 2; ++mt)
        #pragma unroll
        for (int nt = 0; nt < 4; ++nt)
            #pragma unroll
            for (int i = 0; i < 4; ++i) { dh[mt][nt][i] = 0.f; dc[mt][nt][i] = 0.f; }

    {
        #pragma unroll
        for (int q = 0; q < 4; ++q) {
            int idx = t + q * 256;
            int r = idx >> 5, c = (idx & 31) * 4;
            cp16(sbase + (uint32_t)((OFF_AR0 + r * PAR + c) * 4),
                 &Hb[(size_t)r * L_DIM + l0 + c]);
        }
        #pragma unroll
        for (int q = 0; q < 2; ++q) {
            int idx = t + q * 256;
            int r = idx >> 5, c = (idx & 31) * 4;
            cp16(sbase + (uint32_t)((OFF_B0 + r * PBU + c) * 4),
                 &g_Bpk[(r * 256 + c2_0) * 2 + c]);
        }
        cp_commit();
    }

    for (int ch = 0; ch < 8; ++ch) {
        if (ch < 7) {
            const int p = (ch + 1) & 1;
            const int kk = (ch + 1) * 32, k2r0 = (ch + 1) * 16;
            const int offA = p ? OFF_AR1 : OFF_AR0;
            const int offB = p ? OFF_B1 : OFF_B0;
            #pragma unroll
            for (int q = 0; q < 4; ++q) {
                int idx = t + q * 256;
                int r = idx >> 5, c = (idx & 31) * 4;
                cp16(sbase + (uint32_t)((offA + r * PAR + c) * 4),
                     &Hb[(size_t)(kk + r) * L_DIM + l0 + c]);
            }
            #pragma unroll
            for (int q = 0; q < 2; ++q) {
                int idx = t + q * 256;
                int r = idx >> 5, c = (idx & 31) * 4;
                cp16(sbase + (uint32_t)((offB + r * PBU + c) * 4),
                     &g_Bpk[((k2r0 + r) * 256 + c2_0) * 2 + c]);
            }
            cp_commit();
            cp_wait<1>();
        } else {
            cp_wait<0>();
        }
        __syncthreads();

        {
            const float* Ar = smf + ((ch & 1) ? OFF_AR1 : OFF_AR0);
            #pragma unroll
            for (int q = 0; q < 8; ++q) {
                int idx = t + q * 256;
                int k2r = idx >> 7, m = idx & 127;
                float x0 = Ar[(2 * k2r)     * PAR + m];
                float x1 = Ar[(2 * k2r + 1) * PAR + m];
                uint32_t h0, lo0, h1, lo1;
                split_hl(x0, h0, lo0);
                split_hl(x1, h1, lo1);
                uint2 v;
                v.x = h0 | (h1 << 16);
                v.y = lo0 | (lo1 << 16);
                *(uint2*)&smu[OFF_APK + k2r * PAU + 2 * m] = v;
            }
        }
        __syncthreads();

        const uint32_t* Bp = smu + ((ch & 1) ? OFF_B1 : OFF_B0);

        #pragma unroll
        for (int s = 0; s < 2; ++s) {
            const int kr0 = 8 * s + t4, kr1 = kr0 + 4;
            uint32_t ah[2][4], al[2][4];
            #pragma unroll
            for (int mt = 0; mt < 2; ++mt) {
                const int m0 = mw + 16 * mt + g;
                uint2 p0 = *(const uint2*)&smu[OFF_APK + kr0 * PAU + 2 * m0];
                uint2 p1 = *(const uint2*)&smu[OFF_APK + kr0 * PAU + 2 * (m0 + 8)];
                uint2 p2 = *(const uint2*)&smu[OFF_APK + kr1 * PAU + 2 * m0];
                uint2 p3 = *(const uint2*)&smu[OFF_APK + kr1 * PAU + 2 * (m0 + 8)];
                ah[mt][0] = p0.x; al[mt][0] = p0.y;
                ah[mt][1] = p1.x; al[mt][1] = p1.y;
                ah[mt][2] = p2.x; al[mt][2] = p2.y;
                ah[mt][3] = p3.x; al[mt][3] = p3.y;
            }
            uint32_t bh[4][2], bl[4][2];
            #pragma unroll
            for (int q = 0; q < 4; ++q) {
                const int n0 = nw + 8 * q + g;
                uint2 p0 = *(const uint2*)&Bp[kr0 * PBU + 2 * n0];
                uint2 p1 = *(const uint2*)&Bp[kr1 * PBU + 2 * n0];
                bh[q][0] = p0.x; bl[q][0] = p0.y;
                bh[q][1] = p1.x; bl[q][1] = p1.y;
            }
            #pragma unroll
            for (int mt = 0; mt < 2; ++mt)
                #pragma unroll
                for (int q = 0; q < 4; ++q)
                    mma16(dh[mt][q], ah[mt], bh[q]);
            #pragma unroll
            for (int mt = 0; mt < 2; ++mt)
                #pragma unroll
                for (int q = 0; q < 4; ++q)
                    mma16(dc[mt][q], ah[mt], bl[q]);
            #pragma unroll
            for (int mt = 0; mt < 2; ++mt)
                #pragma unroll
                for (int q = 0; q < 4; ++q)
                    mma16(dc[mt][q], al[mt], bh[q]);
        }
    }
    __syncthreads();

    float* Usm = smf;
    float* Ub = g_U + (size_t)b * C_DIM * L_DIM;
    const float inv = 4.8828125e-4f;   // 1/2048
    #pragma unroll
    for (int mt = 0; mt < 2; ++mt) {
        int row0 = mw + 16 * mt + g;
        #pragma unroll
        for (int nt = 0; nt < 4; ++nt) {
            int col0 = nw + 8 * nt + 2 * t4;
            Usm[col0 * UPIT + row0]           = fmaf(dc[mt][nt][0], inv, dh[mt][nt][0]);
            Usm[(col0 + 1) * UPIT + row0]     = fmaf(dc[mt][nt][1], inv, dh[mt][nt][1]);
            Usm[col0 * UPIT + row0 + 8]       = fmaf(dc[mt][nt][2], inv, dh[mt][nt][2]);
            Usm[(col0 + 1) * UPIT + row0 + 8] = fmaf(dc[mt][nt][3], inv, dh[mt][nt][3]);
        }
    }
    __syncthreads();
    for (int i = t; i < 64 * 32; i += 256) {
        int c2 = i >> 5, q = (i & 31) * 4;
        float4 v = *(const float4*)&Usm[c2 * UPIT + q];
        *(float4*)&Ub[(size_t)(c2_0 + c2) * L_DIM + l0 + q] = v;
    }
}

// ---------------- Kernel 3: 32-l blocks, c2-parity split, depth-8 prefetch ----------------
#define K3_SMEM (256 * 36 * 4)   // us[256][36] = 36864 B dynamic

__global__ __launch_bounds__(288, 4) void k3_attn(const float* __restrict__ MSI,
                                                  float* __restrict__ out) {
    extern __shared__ float us[];          // [c2][l] pitch 36
    __shared__ float sc0[288], sc1[288];
    const int t = threadIdx.x;
    const int b = blockIdx.y;
    const int l0 = blockIdx.x * 32;
    const float* Ub = g_U + (size_t)b * C_DIM * L_DIM;

    for (int i = t; i < 256 * 32; i += 288) {
        int c2 = i >> 5, l = i & 31;
        us[c2 * 36 + l] = Ub[(size_t)c2 * L_DIM + l0 + l];
    }
    __syncthreads();

    // 288 m's; threads 0-143 even c2, 144-287 odd c2; each thread 2 m's (float2)
    const int grp = (t >= 144) ? 1 : 0;
    const int tt = t - grp * 144;
    const int ll0 = (2 * tt) / 9, ll1 = (2 * tt + 1) / 9;
    const float* mp = MSI + (size_t)b * C_DIM * LM_DIM + (size_t)l0 * 9 + 2 * tt
                      + (size_t)grp * LM_DIM;
    float acc0 = 0.f, acc1 = 0.f;

    float2 buf[8];
    #pragma unroll
    for (int j = 0; j < 8; ++j)
        buf[j] = __ldg((const float2*)&mp[(size_t)(2 * j) * LM_DIM]);

    const float* u0 = &us[grp * 36 + ll0];
    const float* u1 = &us[grp * 36 + ll1];
    for (int c = 0; c < 120; c += 8) {
        #pragma unroll
        for (int j = 0; j < 8; ++j) {
            float2 nxt = __ldg((const float2*)&mp[(size_t)(2 * (c + 8 + j)) * LM_DIM]);
            acc0 += u0[(c + j) * 72] * buf[j].x;
            acc1 += u1[(c + j) * 72] * buf[j].y;
            buf[j] = nxt;
        }
    }
    #pragma unroll
    for (int j = 0; j < 8; ++j) {
        acc0 += u0[(120 + j) * 72] * buf[j].x;
        acc1 += u1[(120 + j) * 72] * buf[j].y;
    }

    if (grp == 0) { sc0[2 * tt] = acc0; sc0[2 * tt + 1] = acc1; }
    else          { sc1[2 * tt] = acc0; sc1[2 * tt + 1] = acc1; }
    __syncthreads();

    if (t < 32) {
        float best = sc0[t * 9] + sc1[t * 9];
        int bn = 0;
        #pragma unroll
        for (int j = 1; j < 9; ++j) {
            float v = sc0[t * 9 + j] + sc1[t * 9 + j];
            if (v > best) { best = v; bn = j; }   // strict > = first max (jnp.argmax)
        }
        float2 o = make_float2((float)(bn / 3) - 1.f, (float)(bn % 3) - 1.f);
        *(float2*)&out[(size_t)(b * L_DIM + l0 + t) * 2] = o;
    }
}

// ---------------- launch ----------------
extern "C" void kernel_launch(void* const* d_in, const int* in_sizes, int n_in,
                              void* d_out, int out_size) {
    const float* HSI = (const float*)d_in[2];
    const float* MSI = (const float*)d_in[3];
    const float* W1  = (const float*)d_in[4];
    const float* W2  = (const float*)d_in[5];
    float* out = (float*)d_out;

    void* mp = nullptr;
    cudaGetSymbolAddress(&mp, g_M);
    cudaMemsetAsync(mp, 0, C_DIM * C_DIM * sizeof(float), 0);

    k1_M<<<dim3(8, 8, 8), 256>>>(W1, W2);
    k1b_pack<<<128, 256>>>();

    cudaFuncSetAttribute(k2_U, cudaFuncAttributeMaxDynamicSharedMemorySize, K2_SMEM);
    k2_U<<<dim3(32, 4, 4), 256, K2_SMEM>>>(HSI);

    cudaFuncSetAttribute(k3_attn, cudaFuncAttributeMaxDynamicSharedMemorySize, K3_SMEM);
    k3_attn<<<dim3(128, 4), 288, K3_SMEM>>>(MSI, out);
}

// round 13
// speedup vs baseline: 1.1837x; 1.0259x over previous
#include <cuda_runtime.h>
#include <cuda_fp16.h>
#include <cstdint>

#define C_DIM  256
#define L_DIM  4096
#define LM_DIM 36864
#define B_DIM  4

__device__ float    g_M[C_DIM * C_DIM];              // M[c1][c2] fp32
__device__ uint32_t g_Bpk[128 * 256 * 2];            // [k2][n]{hi, lo*2048} f16x2
__device__ float    g_U[B_DIM * C_DIM * L_DIM];      // U[b][c2][l] (x256 scale)

// ---------------- helpers ----------------
__device__ __forceinline__ uint32_t smem_u32(const void* p) {
    uint32_t a;
    asm("{ .reg .u64 t; cvta.to.shared.u64 t, %1; cvt.u32.u64 %0, t; }" : "=r"(a) : "l"(p));
    return a;
}
__device__ __forceinline__ void cp16(uint32_t dst, const void* src) {
    asm volatile("cp.async.cg.shared.global [%0], [%1], 16;" :: "r"(dst), "l"(src) : "memory");
}
__device__ __forceinline__ void cp_commit() {
    asm volatile("cp.async.commit_group;" ::: "memory");
}
template <int N>
__device__ __forceinline__ void cp_wait() {
    asm volatile("cp.async.wait_group %0;" :: "n"(N) : "memory");
}
// split x -> f16 hi + f16 lo*2048 (lo scaled out of subnormal range)
__device__ __forceinline__ void split_hl(float x, uint32_t& h, uint32_t& l) {
    __half hh = __float2half_rn(x);
    float lo = (x - __half2float(hh)) * 2048.0f;
    h = (uint32_t)__half_as_ushort(hh);
    l = (uint32_t)__half_as_ushort(__float2half_rn(lo));
}
__device__ __forceinline__ void mma16(float* d, const uint32_t* a, const uint32_t* b) {
    asm volatile(
        "mma.sync.aligned.m16n8k16.row.col.f32.f16.f16.f32 "
        "{%0,%1,%2,%3}, {%4,%5,%6,%7}, {%8,%9}, {%0,%1,%2,%3};"
        : "+f"(d[0]), "+f"(d[1]), "+f"(d[2]), "+f"(d[3])
        : "r"(a[0]), "r"(a[1]), "r"(a[2]), "r"(a[3]), "r"(b[0]), "r"(b[1]));
}

// ---------------- Kernel 1: M[c1][c2], 8-way k-split + atomicAdd ----------------
__global__ __launch_bounds__(256) void k1_M(const float* __restrict__ W1,
                                            const float* __restrict__ W2) {
    __shared__ float A[32][33];
    __shared__ float Bs[32][33];
    const int t = threadIdx.x;
    const int c2_0 = blockIdx.x * 32, c1_0 = blockIdx.y * 32, kk = blockIdx.z * 32;
    {
        int r = t >> 3, c4 = (t & 7) * 4;
        float4 a = *(const float4*)&W1[(c1_0 + r) * 768 + kk + c4];
        A[r][c4] = a.x; A[r][c4 + 1] = a.y; A[r][c4 + 2] = a.z; A[r][c4 + 3] = a.w;
        float4 b = *(const float4*)&W2[(c2_0 + r) * 768 + 256 + kk + c4];
        Bs[r][c4] = b.x; Bs[r][c4 + 1] = b.y; Bs[r][c4 + 2] = b.z; Bs[r][c4 + 3] = b.w;
    }
    __syncthreads();
    const int ty = t >> 4, tx = t & 15;
    float a00 = 0.f, a01 = 0.f, a10 = 0.f, a11 = 0.f;
    #pragma unroll
    for (int k = 0; k < 32; ++k) {
        float x0 = A[ty * 2][k], x1 = A[ty * 2 + 1][k];
        float y0 = Bs[tx * 2][k], y1 = Bs[tx * 2 + 1][k];
        a00 += x0 * y0; a01 += x0 * y1; a10 += x1 * y0; a11 += x1 * y1;
    }
    atomicAdd(&g_M[(c1_0 + ty * 2)     * 256 + c2_0 + tx * 2],     a00);
    atomicAdd(&g_M[(c1_0 + ty * 2)     * 256 + c2_0 + tx * 2 + 1], a01);
    atomicAdd(&g_M[(c1_0 + ty * 2 + 1) * 256 + c2_0 + tx * 2],     a10);
    atomicAdd(&g_M[(c1_0 + ty * 2 + 1) * 256 + c2_0 + tx * 2 + 1], a11);
}

// ---------------- Kernel 1b: pack M*256 -> f16 {hi, lo*2048} k-pairs [k2][n] ----------------
__global__ __launch_bounds__(256) void k1b_pack() {
    const int idx = blockIdx.x * 256 + threadIdx.x;
    const int k2 = idx >> 8, n = idx & 255;
    float x0 = g_M[(2 * k2)     * 256 + n] * 256.0f;
    float x1 = g_M[(2 * k2 + 1) * 256 + n] * 256.0f;
    uint32_t h0, l0, h1, l1;
    split_hl(x0, h0, l0);
    split_hl(x1, h1, l1);
    uint2 v;
    v.x = h0 | (h1 << 16);
    v.y = l0 | (l1 << 16);
    *(uint2*)&g_Bpk[idx * 2] = v;
}

// ---------------- Kernel 2: 64 l x 256 c2 blocks, A read once, B from L2 ----------------
// smem u32: APK 16x136 | AR0 32x68 (f32) | AR1 | B0 16x520 | B1
#define PAU 136
#define PAR 68
#define PBU 520
#define OFF_APK 0
#define OFF_AR0 2176
#define OFF_AR1 4352
#define OFF_B0  6528
#define OFF_B1  14848
#define K2_F    23168
#define K2_SMEM (K2_F * 4)                 // 92672 B
#define UPIT 68

__global__ __launch_bounds__(512, 1) void k2_U(const float* __restrict__ HSI) {
    extern __shared__ uint32_t smu[];
    float* smf = (float*)smu;
    const int t = threadIdx.x, wid = t >> 5, lane = t & 31;
    const int g = lane >> 2, t4 = lane & 3;
    const int b = blockIdx.y, l0 = blockIdx.x * 64;
    const float* Hb = HSI + (size_t)b * C_DIM * L_DIM;
    const uint32_t sbase = smem_u32(smu);
    const int mw = (wid >> 3) * 32;        // 2 m-warps (32 l each)
    const int nw = (wid & 7) * 32;         // 8 n-warps (32 c2 each)

    float dh[2][4][4], dc[2][4][4];
    #pragma unroll
    for (int mt = 0; mt < 2; ++mt)
        #pragma unroll
        for (int nt = 0; nt < 4; ++nt)
            #pragma unroll
            for (int i = 0; i < 4; ++i) { dh[mt][nt][i] = 0.f; dc[mt][nt][i] = 0.f; }

    // chunk 0 copies
    {
        {   // A raw: 32 rows x 16 quads (64 f32/row)
            int r = t >> 4, c = (t & 15) * 4;
            cp16(sbase + (uint32_t)((OFF_AR0 + r * PAR + c) * 4),
                 &Hb[(size_t)r * L_DIM + l0 + c]);
        }
        #pragma unroll
        for (int q = 0; q < 4; ++q) {   // B pack: 16 rows x 128 quads (512 u32/row)
            int idx = t + q * 512;
            int r = idx >> 7, c = (idx & 127) * 4;
            cp16(sbase + (uint32_t)((OFF_B0 + r * PBU + c) * 4), &g_Bpk[r * 512 + c]);
        }
        cp_commit();
    }

    for (int ch = 0; ch < 8; ++ch) {
        if (ch < 7) {
            const int p = (ch + 1) & 1;
            const int kk = (ch + 1) * 32, k2r0 = (ch + 1) * 16;
            const int offA = p ? OFF_AR1 : OFF_AR0;
            const int offB = p ? OFF_B1 : OFF_B0;
            {
                int r = t >> 4, c = (t & 15) * 4;
                cp16(sbase + (uint32_t)((offA + r * PAR + c) * 4),
                     &Hb[(size_t)(kk + r) * L_DIM + l0 + c]);
            }
            #pragma unroll
            for (int q = 0; q < 4; ++q) {
                int idx = t + q * 512;
                int r = idx >> 7, c = (idx & 127) * 4;
                cp16(sbase + (uint32_t)((offB + r * PBU + c) * 4),
                     &g_Bpk[(k2r0 + r) * 512 + c]);
            }
            cp_commit();
            cp_wait<1>();
        } else {
            cp_wait<0>();
        }
        __syncthreads();   // prev compute done (APK reusable) + chunk ch landed

        // stage-split A: raw f32 [32][64] -> APK [kpair 16][m 64] {hi, lo*2048}
        {
            const float* Ar = smf + ((ch & 1) ? OFF_AR1 : OFF_AR0);
            #pragma unroll
            for (int q = 0; q < 2; ++q) {
                int idx = t + q * 512;
                int k2r = idx >> 6, m = idx & 63;
                float x0 = Ar[(2 * k2r)     * PAR + m];
                float x1 = Ar[(2 * k2r + 1) * PAR + m];
                uint32_t h0, lo0, h1, lo1;
                split_hl(x0, h0, lo0);
                split_hl(x1, h1, lo1);
                uint2 v;
                v.x = h0 | (h1 << 16);
                v.y = lo0 | (lo1 << 16);
                *(uint2*)&smu[OFF_APK + k2r * PAU + 2 * m] = v;
            }
        }
        __syncthreads();

        const uint32_t* Bp = smu + ((ch & 1) ? OFF_B1 : OFF_B0);

        #pragma unroll
        for (int s = 0; s < 2; ++s) {
            const int kr0 = 8 * s + t4, kr1 = kr0 + 4;
            uint32_t ah[2][4], al[2][4];
            #pragma unroll
            for (int mt = 0; mt < 2; ++mt) {
                const int m0 = mw + 16 * mt + g;
                uint2 p0 = *(const uint2*)&smu[OFF_APK + kr0 * PAU + 2 * m0];
                uint2 p1 = *(const uint2*)&smu[OFF_APK + kr0 * PAU + 2 * (m0 + 8)];
                uint2 p2 = *(const uint2*)&smu[OFF_APK + kr1 * PAU + 2 * m0];
                uint2 p3 = *(const uint2*)&smu[OFF_APK + kr1 * PAU + 2 * (m0 + 8)];
                ah[mt][0] = p0.x; al[mt][0] = p0.y;
                ah[mt][1] = p1.x; al[mt][1] = p1.y;
                ah[mt][2] = p2.x; al[mt][2] = p2.y;
                ah[mt][3] = p3.x; al[mt][3] = p3.y;
            }
            uint32_t bh[4][2], bl[4][2];
            #pragma unroll
            for (int q = 0; q < 4; ++q) {
                const int n0 = nw + 8 * q + g;
                uint2 p0 = *(const uint2*)&Bp[kr0 * PBU + 2 * n0];
                uint2 p1 = *(const uint2*)&Bp[kr1 * PBU + 2 * n0];
                bh[q][0] = p0.x; bl[q][0] = p0.y;
                bh[q][1] = p1.x; bl[q][1] = p1.y;
            }
            #pragma unroll
            for (int mt = 0; mt < 2; ++mt)
                #pragma unroll
                for (int q = 0; q < 4; ++q)
                    mma16(dh[mt][q], ah[mt], bh[q]);
            #pragma unroll
            for (int mt = 0; mt < 2; ++mt)
                #pragma unroll
                for (int q = 0; q < 4; ++q)
                    mma16(dc[mt][q], ah[mt], bl[q]);
            #pragma unroll
            for (int mt = 0; mt < 2; ++mt)
                #pragma unroll
                for (int q = 0; q < 4; ++q)
                    mma16(dc[mt][q], al[mt], bh[q]);
        }
    }
    __syncthreads();

    // combine + epilogue: Usm[c2 256][l 64] pitch 68, coalesced stores
    float* Usm = smf;
    float* Ub = g_U + (size_t)b * C_DIM * L_DIM;
    const float inv = 4.8828125e-4f;   // 1/2048
    #pragma unroll
    for (int mt = 0; mt < 2; ++mt) {
        int row0 = mw + 16 * mt + g;
        #pragma unroll
        for (int nt = 0; nt < 4; ++nt) {
            int col0 = nw + 8 * nt + 2 * t4;
            Usm[col0 * UPIT + row0]           = fmaf(dc[mt][nt][0], inv, dh[mt][nt][0]);
            Usm[(col0 + 1) * UPIT + row0]     = fmaf(dc[mt][nt][1], inv, dh[mt][nt][1]);
            Usm[col0 * UPIT + row0 + 8]       = fmaf(dc[mt][nt][2], inv, dh[mt][nt][2]);
            Usm[(col0 + 1) * UPIT + row0 + 8] = fmaf(dc[mt][nt][3], inv, dh[mt][nt][3]);
        }
    }
    __syncthreads();
    #pragma unroll
    for (int q = 0; q < 8; ++q) {
        int i = t + q * 512;               // 4096 quads = 256 c2 x 16 quads
        int c2 = i >> 4, qq = (i & 15) * 4;
        float4 v = *(const float4*)&Usm[c2 * UPIT + qq];
        *(float4*)&Ub[(size_t)c2 * L_DIM + l0 + qq] = v;
    }
}

// ---------------- Kernel 3: 32-l blocks, c2-parity split, depth-8 prefetch (r12-proven) ----------------
#define K3_SMEM (256 * 36 * 4)   // us[256][36]

__global__ __launch_bounds__(288, 4) void k3_attn(const float* __restrict__ MSI,
                                                  float* __restrict__ out) {
    extern __shared__ float us[];          // [c2][l] pitch 36
    __shared__ float sc0[288], sc1[288];
    const int t = threadIdx.x;
    const int b = blockIdx.y;
    const int l0 = blockIdx.x * 32;
    const float* Ub = g_U + (size_t)b * C_DIM * L_DIM;

    for (int i = t; i < 256 * 32; i += 288) {
        int c2 = i >> 5, l = i & 31;
        us[c2 * 36 + l] = Ub[(size_t)c2 * L_DIM + l0 + l];
    }
    __syncthreads();

    const int grp = (t >= 144) ? 1 : 0;
    const int tt = t - grp * 144;
    const int ll0 = (2 * tt) / 9, ll1 = (2 * tt + 1) / 9;
    const float* mp = MSI + (size_t)b * C_DIM * LM_DIM + (size_t)l0 * 9 + 2 * tt
                      + (size_t)grp * LM_DIM;
    float acc0 = 0.f, acc1 = 0.f;

    float2 buf[8];
    #pragma unroll
    for (int j = 0; j < 8; ++j)
        buf[j] = __ldg((const float2*)&mp[(size_t)(2 * j) * LM_DIM]);

    const float* u0 = &us[grp * 36 + ll0];
    const float* u1 = &us[grp * 36 + ll1];
    for (int c = 0; c < 120; c += 8) {
        #pragma unroll
        for (int j = 0; j < 8; ++j) {
            float2 nxt = __ldg((const float2*)&mp[(size_t)(2 * (c + 8 + j)) * LM_DIM]);
            acc0 += u0[(c + j) * 72] * buf[j].x;
            acc1 += u1[(c + j) * 72] * buf[j].y;
            buf[j] = nxt;
        }
    }
    #pragma unroll
    for (int j = 0; j < 8; ++j) {
        acc0 += u0[(120 + j) * 72] * buf[j].x;
        acc1 += u1[(120 + j) * 72] * buf[j].y;
    }

    if (grp == 0) { sc0[2 * tt] = acc0; sc0[2 * tt + 1] = acc1; }
    else          { sc1[2 * tt] = acc0; sc1[2 * tt + 1] = acc1; }
    __syncthreads();

    if (t < 32) {
        float best = sc0[t * 9] + sc1[t * 9];
        int bn = 0;
        #pragma unroll
        for (int j = 1; j < 9; ++j) {
            float v = sc0[t * 9 + j] + sc1[t * 9 + j];
            if (v > best) { best = v; bn = j; }   // strict > = first max (jnp.argmax)
        }
        float2 o = make_float2((float)(bn / 3) - 1.f, (float)(bn % 3) - 1.f);
        *(float2*)&out[(size_t)(b * L_DIM + l0 + t) * 2] = o;
    }
}

// ---------------- launch ----------------
extern "C" void kernel_launch(void* const* d_in, const int* in_sizes, int n_in,
                              void* d_out, int out_size) {
    const float* HSI = (const float*)d_in[2];
    const float* MSI = (const float*)d_in[3];
    const float* W1  = (const float*)d_in[4];
    const float* W2  = (const float*)d_in[5];
    float* out = (float*)d_out;

    void* mp = nullptr;
    cudaGetSymbolAddress(&mp, g_M);
    cudaMemsetAsync(mp, 0, C_DIM * C_DIM * sizeof(float), 0);

    k1_M<<<dim3(8, 8, 8), 256>>>(W1, W2);
    k1b_pack<<<128, 256>>>();

    cudaFuncSetAttribute(k2_U, cudaFuncAttributeMaxDynamicSharedMemorySize, K2_SMEM);
    k2_U<<<dim3(64, 4), 512, K2_SMEM>>>(HSI);

    cudaFuncSetAttribute(k3_attn, cudaFuncAttributeMaxDynamicSharedMemorySize, K3_SMEM);
    k3_attn<<<dim3(128, 4), 288, K3_SMEM>>>(MSI, out);
}

// round 15
// speedup vs baseline: 1.2157x; 1.0270x over previous
#include <cuda_runtime.h>
#include <cuda_fp16.h>
#include <cstdint>

#define C_DIM  256
#define L_DIM  4096
#define LM_DIM 36864
#define B_DIM  4

__device__ uint32_t g_Bpk[128 * 256 * 2];            // [kpair][n]{hi, lo*2048} f16x2 (M*256)
__device__ float    g_U[B_DIM * C_DIM * L_DIM];      // U[b][c2][l] (x256 scale)

// ---------------- helpers ----------------
__device__ __forceinline__ uint32_t smem_u32(const void* p) {
    uint32_t a;
    asm("{ .reg .u64 t; cvta.to.shared.u64 t, %1; cvt.u32.u64 %0, t; }" : "=r"(a) : "l"(p));
    return a;
}
__device__ __forceinline__ void cp16(uint32_t dst, const void* src) {
    asm volatile("cp.async.cg.shared.global [%0], [%1], 16;" :: "r"(dst), "l"(src) : "memory");
}
__device__ __forceinline__ void cp_commit() {
    asm volatile("cp.async.commit_group;" ::: "memory");
}
template <int N>
__device__ __forceinline__ void cp_wait() {
    asm volatile("cp.async.wait_group %0;" :: "n"(N) : "memory");
}
// split x -> f16 hi + f16 lo*2048 (lo scaled out of subnormal range)
__device__ __forceinline__ void split_hl(float x, uint32_t& h, uint32_t& l) {
    __half hh = __float2half_rn(x);
    float lo = (x - __half2float(hh)) * 2048.0f;
    h = (uint32_t)__half_as_ushort(hh);
    l = (uint32_t)__half_as_ushort(__float2half_rn(lo));
}
__device__ __forceinline__ void mma16(float* d, const uint32_t* a, const uint32_t* b) {
    asm volatile(
        "mma.sync.aligned.m16n8k16.row.col.f32.f16.f16.f32 "
        "{%0,%1,%2,%3}, {%4,%5,%6,%7}, {%8,%9}, {%0,%1,%2,%3};"
        : "+f"(d[0]), "+f"(d[1]), "+f"(d[2]), "+f"(d[3])
        : "r"(a[0]), "r"(a[1]), "r"(a[2]), "r"(a[3]), "r"(b[0]), "r"(b[1]));
}

// ---------------- Kernel 1 (fused): M tile + f16 hi/lo pack ----------------
// Block: 32 c1 x 32 c2, full K=256 in smem. Pitch 260 floats: 1040 B/row,
// 16B-aligned for cp.async (260 % 4 == 0). 4-way LDS conflict on B reads is
// acceptable for this tiny kernel.
#define K1_PITCH 260
#define K1_SMEM  (2 * 32 * K1_PITCH * 4)   // 66560 B dynamic

__global__ __launch_bounds__(256) void k1_M(const float* __restrict__ W1,
                                            const float* __restrict__ W2) {
    extern __shared__ float k1s[];
    float* As = k1s;                       // [c1_local][k]
    float* Bs = k1s + 32 * K1_PITCH;       // [c2_local][k]
    const int t = threadIdx.x;
    const int c1_0 = blockIdx.y * 32, c2_0 = blockIdx.x * 32;
    const uint32_t sbase = smem_u32(k1s);

    #pragma unroll
    for (int q = 0; q < 8; ++q) {          // 2048 quads each array
        int idx = t + q * 256;
        int r = idx >> 6, c = (idx & 63) * 4;
        cp16(sbase + (uint32_t)((r * K1_PITCH + c) * 4),
             &W1[(c1_0 + r) * 768 + c]);
        cp16(sbase + (uint32_t)((32 * K1_PITCH + r * K1_PITCH + c) * 4),
             &W2[(c2_0 + r) * 768 + 256 + c]);
    }
    cp_commit();
    cp_wait<0>();
    __syncthreads();

    const int ty = t >> 4, tx = t & 15;
    const float* a0p = As + (2 * ty) * K1_PITCH;
    const float* a1p = As + (2 * ty + 1) * K1_PITCH;
    const float* b0p = Bs + (2 * tx) * K1_PITCH;
    const float* b1p = Bs + (2 * tx + 1) * K1_PITCH;
    float a00 = 0.f, a01 = 0.f, a10 = 0.f, a11 = 0.f;
    #pragma unroll 8
    for (int k = 0; k < 256; ++k) {
        float x0 = a0p[k], x1 = a1p[k];
        float y0 = b0p[k], y1 = b1p[k];
        a00 += x0 * y0; a01 += x0 * y1; a10 += x1 * y0; a11 += x1 * y1;
    }

    // pack: this thread owns kpair = c1_0/2 + ty for c2 = c2_0 + 2tx + {0,1}
    const int kp = (c1_0 >> 1) + ty;
    {
        float x0 = a00 * 256.0f, x1 = a10 * 256.0f;    // c2 = c2_0+2tx
        uint32_t h0, l0, h1, l1;
        split_hl(x0, h0, l0);
        split_hl(x1, h1, l1);
        uint2 v; v.x = h0 | (h1 << 16); v.y = l0 | (l1 << 16);
        *(uint2*)&g_Bpk[((size_t)kp * 256 + c2_0 + 2 * tx) * 2] = v;
    }
    {
        float x0 = a01 * 256.0f, x1 = a11 * 256.0f;    // c2 = c2_0+2tx+1
        uint32_t h0, l0, h1, l1;
        split_hl(x0, h0, l0);
        split_hl(x1, h1, l1);
        uint2 v; v.x = h0 | (h1 << 16); v.y = l0 | (l1 << 16);
        *(uint2*)&g_Bpk[((size_t)kp * 256 + c2_0 + 2 * tx + 1) * 2] = v;
    }
}

// ---------------- Kernel 2: 64 l x 128 c2, 256 thr, 2 CTA/SM ----------------
// smem u32: APK 16x136 | AR0 32x68 (f32) | AR1 | B0 16x264 | B1
#define PAU 136
#define PAR 68
#define PBU 264
#define OFF_APK 0
#define OFF_AR0 2176
#define OFF_AR1 4352
#define OFF_B0  6528
#define OFF_B1  10752
#define K2_F    14976
#define K2_SMEM (K2_F * 4)                 // 59904 B
#define UPIT 68

__global__ __launch_bounds__(256, 2) void k2_U(const float* __restrict__ HSI) {
    extern __shared__ uint32_t smu[];
    float* smf = (float*)smu;
    const int t = threadIdx.x, wid = t >> 5, lane = t & 31;
    const int g = lane >> 2, t4 = lane & 3;
    const int b = blockIdx.z, c2_0 = blockIdx.y * 128, l0 = blockIdx.x * 64;
    const float* Hb = HSI + (size_t)b * C_DIM * L_DIM;
    const uint32_t sbase = smem_u32(smu);
    const int mw = (wid >> 2) * 32;        // 2 m-warps (32 l each)
    const int nw = (wid & 3) * 32;         // 4 n-warps (32 c2 each)

    float dh[2][4][4], dc[2][4][4];
    #pragma unroll
    for (int mt = 0; mt < 2; ++mt)
        #pragma unroll
        for (int nt = 0; nt < 4; ++nt)
            #pragma unroll
            for (int i = 0; i < 4; ++i) { dh[mt][nt][i] = 0.f; dc[mt][nt][i] = 0.f; }

    // chunk 0 copies
    {
        #pragma unroll
        for (int q = 0; q < 2; ++q) {      // A raw: 32 rows x 16 quads (64 f32/row)
            int idx = t + q * 256;
            int r = idx >> 4, c = (idx & 15) * 4;
            cp16(sbase + (uint32_t)((OFF_AR0 + r * PAR + c) * 4),
                 &Hb[(size_t)r * L_DIM + l0 + c]);
        }
        #pragma unroll
        for (int q = 0; q < 4; ++q) {      // B pack: 16 rows x 64 quads (256 u32/row)
            int idx = t + q * 256;
            int r = idx >> 6, c = (idx & 63) * 4;
            cp16(sbase + (uint32_t)((OFF_B0 + r * PBU + c) * 4),
                 &g_Bpk[((size_t)r * 256 + c2_0) * 2 + c]);
        }
        cp_commit();
    }

    for (int ch = 0; ch < 8; ++ch) {
        if (ch < 7) {
            const int p = (ch + 1) & 1;
            const int kk = (ch + 1) * 32, k2r0 = (ch + 1) * 16;
            const int offA = p ? OFF_AR1 : OFF_AR0;
            const int offB = p ? OFF_B1 : OFF_B0;
            #pragma unroll
            for (int q = 0; q < 2; ++q) {
                int idx = t + q * 256;
                int r = idx >> 4, c = (idx & 15) * 4;
                cp16(sbase + (uint32_t)((offA + r * PAR + c) * 4),
                     &Hb[(size_t)(kk + r) * L_DIM + l0 + c]);
            }
            #pragma unroll
            for (int q = 0; q < 4; ++q) {
                int idx = t + q * 256;
                int r = idx >> 6, c = (idx & 63) * 4;
                cp16(sbase + (uint32_t)((offB + r * PBU + c) * 4),
                     &g_Bpk[((size_t)(k2r0 + r) * 256 + c2_0) * 2 + c]);
            }
            cp_commit();
            cp_wait<1>();
        } else {
            cp_wait<0>();
        }
        __syncthreads();   // prev compute done (APK reusable) + chunk ch landed

        // stage-split A: raw f32 [32][64] -> APK [kpair 16][m 64] {hi, lo*2048}
        {
            const float* Ar = smf + ((ch & 1) ? OFF_AR1 : OFF_AR0);
            #pragma unroll
            for (int q = 0; q < 4; ++q) {
                int idx = t + q * 256;
                int k2r = idx >> 6, m = idx & 63;
                float x0 = Ar[(2 * k2r)     * PAR + m];
                float x1 = Ar[(2 * k2r + 1) * PAR + m];
                uint32_t h0, lo0, h1, lo1;
                split_hl(x0, h0, lo0);
                split_hl(x1, h1, lo1);
                uint2 v;
                v.x = h0 | (h1 << 16);
                v.y = lo0 | (lo1 << 16);
                *(uint2*)&smu[OFF_APK + k2r * PAU + 2 * m] = v;
            }
        }
        __syncthreads();

        const uint32_t* Bp = smu + ((ch & 1) ? OFF_B1 : OFF_B0);

        #pragma unroll
        for (int s = 0; s < 2; ++s) {
            const int kr0 = 8 * s + t4, kr1 = kr0 + 4;
            uint32_t ah[2][4], al[2][4];
            #pragma unroll
            for (int mt = 0; mt < 2; ++mt) {
                const int m0 = mw + 16 * mt + g;
                uint2 p0 = *(const uint2*)&smu[OFF_APK + kr0 * PAU + 2 * m0];
                uint2 p1 = *(const uint2*)&smu[OFF_APK + kr0 * PAU + 2 * (m0 + 8)];
                uint2 p2 = *(const uint2*)&smu[OFF_APK + kr1 * PAU + 2 * m0];
                uint2 p3 = *(const uint2*)&smu[OFF_APK + kr1 * PAU + 2 * (m0 + 8)];
                ah[mt][0] = p0.x; al[mt][0] = p0.y;
                ah[mt][1] = p1.x; al[mt][1] = p1.y;
                ah[mt][2] = p2.x; al[mt][2] = p2.y;
                ah[mt][3] = p3.x; al[mt][3] = p3.y;
            }
            uint32_t bh[4][2], bl[4][2];
            #pragma unroll
            for (int q = 0; q < 4; ++q) {
                const int n0 = nw + 8 * q + g;
                uint2 p0 = *(const uint2*)&Bp[kr0 * PBU + 2 * n0];
                uint2 p1 = *(const uint2*)&Bp[kr1 * PBU + 2 * n0];
                bh[q][0] = p0.x; bl[q][0] = p0.y;
                bh[q][1] = p1.x; bl[q][1] = p1.y;
            }
            #pragma unroll
            for (int mt = 0; mt < 2; ++mt)
                #pragma unroll
                for (int q = 0; q < 4; ++q)
                    mma16(dh[mt][q], ah[mt], bh[q]);
            #pragma unroll
            for (int mt = 0; mt < 2; ++mt)
                #pragma unroll
                for (int q = 0; q < 4; ++q)
                    mma16(dc[mt][q], ah[mt], bl[q]);
            #pragma unroll
            for (int mt = 0; mt < 2; ++mt)
                #pragma unroll
                for (int q = 0; q < 4; ++q)
                    mma16(dc[mt][q], al[mt], bh[q]);
        }
    }
    __syncthreads();

    // combine + epilogue: Usm[c2 128][l 64] pitch 68, coalesced stores
    float* Usm = smf;
    float* Ub = g_U + (size_t)b * C_DIM * L_DIM;
    const float inv = 4.8828125e-4f;   // 1/2048
    #pragma unroll
    for (int mt = 0; mt < 2; ++mt) {
        int row0 = mw + 16 * mt + g;
        #pragma unroll
        for (int nt = 0; nt < 4; ++nt) {
            int col0 = nw + 8 * nt + 2 * t4;
            Usm[col0 * UPIT + row0]           = fmaf(dc[mt][nt][0], inv, dh[mt][nt][0]);
            Usm[(col0 + 1) * UPIT + row0]     = fmaf(dc[mt][nt][1], inv, dh[mt][nt][1]);
            Usm[col0 * UPIT + row0 + 8]       = fmaf(dc[mt][nt][2], inv, dh[mt][nt][2]);
            Usm[(col0 + 1) * UPIT + row0 + 8] = fmaf(dc[mt][nt][3], inv, dh[mt][nt][3]);
        }
    }
    __syncthreads();
    #pragma unroll
    for (int q = 0; q < 8; ++q) {
        int i = t + q * 256;               // 2048 quads = 128 c2 x 16 quads
        int c2 = i >> 4, qq = (i & 15) * 4;
        float4 v = *(const float4*)&Usm[c2 * UPIT + qq];
        *(float4*)&Ub[(size_t)(c2_0 + c2) * L_DIM + l0 + qq] = v;
    }
}

// ---------------- Kernel 3: 32-l blocks, c2-parity split, depth-8 prefetch (r12-proven) ----------------
#define K3_SMEM (256 * 36 * 4)   // us[256][36]

__global__ __launch_bounds__(288, 4) void k3_attn(const float* __restrict__ MSI,
                                                  float* __restrict__ out) {
    extern __shared__ float us[];          // [c2][l] pitch 36
    __shared__ float sc0[288], sc1[288];
    const int t = threadIdx.x;
    const int b = blockIdx.y;
    const int l0 = blockIdx.x * 32;
    const float* Ub = g_U + (size_t)b * C_DIM * L_DIM;

    for (int i = t; i < 256 * 32; i += 288) {
        int c2 = i >> 5, l = i & 31;
        us[c2 * 36 + l] = Ub[(size_t)c2 * L_DIM + l0 + l];
    }
    __syncthreads();

    const int grp = (t >= 144) ? 1 : 0;
    const int tt = t - grp * 144;
    const int ll0 = (2 * tt) / 9, ll1 = (2 * tt + 1) / 9;
    const float* mp = MSI + (size_t)b * C_DIM * LM_DIM + (size_t)l0 * 9 + 2 * tt
                      + (size_t)grp * LM_DIM;
    float acc0 = 0.f, acc1 = 0.f;

    float2 buf[8];
    #pragma unroll
    for (int j = 0; j < 8; ++j)
        buf[j] = __ldg((const float2*)&mp[(size_t)(2 * j) * LM_DIM]);

    const float* u0 = &us[grp * 36 + ll0];
    const float* u1 = &us[grp * 36 + ll1];
    for (int c = 0; c < 120; c += 8) {
        #pragma unroll
        for (int j = 0; j < 8; ++j) {
            float2 nxt = __ldg((const float2*)&mp[(size_t)(2 * (c + 8 + j)) * LM_DIM]);
            acc0 += u0[(c + j) * 72] * buf[j].x;
            acc1 += u1[(c + j) * 72] * buf[j].y;
            buf[j] = nxt;
        }
    }
    #pragma unroll
    for (int j = 0; j < 8; ++j) {
        acc0 += u0[(120 + j) * 72] * buf[j].x;
        acc1 += u1[(120 + j) * 72] * buf[j].y;
    }

    if (grp == 0) { sc0[2 * tt] = acc0; sc0[2 * tt + 1] = acc1; }
    else          { sc1[2 * tt] = acc0; sc1[2 * tt + 1] = acc1; }
    __syncthreads();

    if (t < 32) {
        float best = sc0[t * 9] + sc1[t * 9];
        int bn = 0;
        #pragma unroll
        for (int j = 1; j < 9; ++j) {
            float v = sc0[t * 9 + j] + sc1[t * 9 + j];
            if (v > best) { best = v; bn = j; }   // strict > = first max (jnp.argmax)
        }
        float2 o = make_float2((float)(bn / 3) - 1.f, (float)(bn % 3) - 1.f);
        *(float2*)&out[(size_t)(b * L_DIM + l0 + t) * 2] = o;
    }
}

// ---------------- launch ----------------
extern "C" void kernel_launch(void* const* d_in, const int* in_sizes, int n_in,
                              void* d_out, int out_size) {
    const float* HSI = (const float*)d_in[2];
    const float* MSI = (const float*)d_in[3];
    const float* W1  = (const float*)d_in[4];
    const float* W2  = (const float*)d_in[5];
    float* out = (float*)d_out;

    cudaFuncSetAttribute(k1_M, cudaFuncAttributeMaxDynamicSharedMemorySize, K1_SMEM);
    k1_M<<<dim3(8, 8), 256, K1_SMEM>>>(W1, W2);

    cudaFuncSetAttribute(k2_U, cudaFuncAttributeMaxDynamicSharedMemorySize, K2_SMEM);
    k2_U<<<dim3(64, 2, 4), 256, K2_SMEM>>>(HSI);

    cudaFuncSetAttribute(k3_attn, cudaFuncAttributeMaxDynamicSharedMemorySize, K3_SMEM);
    k3_attn<<<dim3(128, 4), 288, K3_SMEM>>>(MSI, out);
}